// round 17
// baseline (speedup 1.0000x reference)
#include <cuda_runtime.h>
#include <math.h>

#define NN 50000
#define EE 800000
#define H 64
#define H2 128
#define EPS 1e-7f
#define LN_EPS 1e-5f

// ---------------- device scratch (no allocations allowed) ----------------
__device__ float g_h[NN * H];
__device__ float g_y[NN * H];
__device__ float g_t0[NN * H];
__device__ int g_deg[NN];
__device__ int g_rowptr[NN + 1];
__device__ int g_fill[NN];
__device__ int g_csr[EE];
__device__ unsigned g_gmax[16];

// ---------------- helpers ----------------
__device__ __forceinline__ unsigned fenc(float f) {
    unsigned u = __float_as_uint(f);
    return (u & 0x80000000u) ? ~u : (u | 0x80000000u);
}
__device__ __forceinline__ float fdec(unsigned v) {
    return (v & 0x80000000u) ? __uint_as_float(v ^ 0x80000000u)
                             : __uint_as_float(~v);
}
__device__ __forceinline__ float red16(float v) {
    v += __shfl_xor_sync(0xffffffffu, v, 8, 16);
    v += __shfl_xor_sync(0xffffffffu, v, 4, 16);
    v += __shfl_xor_sync(0xffffffffu, v, 2, 16);
    v += __shfl_xor_sync(0xffffffffu, v, 1, 16);
    return v;
}
// packed f32x2 FMA (only reachable via PTX)
__device__ __forceinline__ unsigned long long pack2(float lo, float hi) {
    unsigned long long r;
    asm("mov.b64 %0, {%1,%2};" : "=l"(r) : "f"(lo), "f"(hi));
    return r;
}
__device__ __forceinline__ void unpack2(unsigned long long v, float& lo, float& hi) {
    asm("mov.b64 {%0,%1}, %2;" : "=f"(lo), "=f"(hi) : "l"(v));
}
__device__ __forceinline__ unsigned long long ffma2(unsigned long long a,
                                                    unsigned long long b,
                                                    unsigned long long c) {
    unsigned long long d;
    asm("fma.rn.f32x2 %0, %1, %2, %3;" : "=l"(d) : "l"(a), "l"(b), "l"(c));
    return d;
}

// ---------------- init: zero degree counters + gmax ----------------
__global__ void k_init() {
    int i = blockIdx.x * 256 + threadIdx.x;
    if (i < NN) g_deg[i] = 0;
    if (blockIdx.x == 0 && threadIdx.x < 16) g_gmax[threadIdx.x] = 0u;
}

// ---------------- CSR build ----------------
__global__ void k_deg(const int* __restrict__ ei) {
    int e = blockIdx.x * 256 + threadIdx.x;
    if (e < EE) atomicAdd(&g_deg[ei[EE + e]], 1);
}

__global__ void k_scan() {
    __shared__ int warp_sums[32];
    __shared__ int s_carry;
    const int tid = threadIdx.x, lane = tid & 31, wid = tid >> 5;
    if (tid == 0) { s_carry = 0; g_rowptr[0] = 0; }
    __syncthreads();
    const int PER_T = 8, CH = 1024 * PER_T;
    for (int base = 0; base < NN; base += CH) {
        int idx0 = base + tid * PER_T;
        int v[PER_T], p[PER_T], s = 0;
#pragma unroll
        for (int j = 0; j < PER_T; j++) {
            int i = idx0 + j;
            v[j] = (i < NN) ? g_deg[i] : 0;
            s += v[j];
            p[j] = s;
        }
        int ws = s;
#pragma unroll
        for (int o = 1; o < 32; o <<= 1) {
            int t = __shfl_up_sync(0xffffffffu, ws, o);
            if (lane >= o) ws += t;
        }
        if (lane == 31) warp_sums[wid] = ws;
        __syncthreads();
        if (wid == 0) {
            int x = warp_sums[lane];
            int xs = x;
#pragma unroll
            for (int o = 1; o < 32; o <<= 1) {
                int t = __shfl_up_sync(0xffffffffu, xs, o);
                if (lane >= o) xs += t;
            }
            warp_sums[lane] = xs - x;  // exclusive
        }
        __syncthreads();
        int carry = s_carry;
        int excl = carry + warp_sums[wid] + (ws - s);
#pragma unroll
        for (int j = 0; j < PER_T; j++) {
            int i = idx0 + j;
            if (i < NN) {
                g_rowptr[i + 1] = excl + p[j];
                g_fill[i] = excl + p[j] - v[j];
            }
        }
        __syncthreads();
        if (tid == 1023) s_carry = excl + s;
        __syncthreads();
    }
}

__global__ void k_fill(const int* __restrict__ ei) {
    int e = blockIdx.x * 256 + threadIdx.x;
    if (e < EE) {
        int src = ei[e];
        int dst = ei[EE + e];
        int pos = atomicAdd(&g_fill[dst], 1);
        g_csr[pos] = src;
    }
}

// ---------------- node encoder (128-node tile, 4 nodes x 8 cols/thread) -
__global__ __launch_bounds__(256) void k_encoder(const float* __restrict__ x,
                                                 const float* __restrict__ W,
                                                 const float* __restrict__ b) {
    __shared__ float Xs[128 * 36];
    __shared__ float Ws[32 * 64];
    __shared__ float bs[64];
    const int tid = threadIdx.x;
    const int n0 = blockIdx.x * 128;
#pragma unroll
    for (int i = tid * 4; i < 4096; i += 1024) {
        int r = i >> 5, c = i & 31;
        float4 v = make_float4(0.f, 0.f, 0.f, 0.f);
        if (n0 + r < NN) v = *(const float4*)&x[(n0 + r) * 32 + c];
        *(float4*)&Xs[r * 36 + c] = v;
    }
#pragma unroll
    for (int i = tid * 4; i < 2048; i += 1024)
        *(float4*)&Ws[i] = *(const float4*)&W[i];
    if (tid < 64) bs[tid] = b[tid];
    __syncthreads();

    const int ng = tid >> 3;         // nodes ng + 32*j
    const int c0 = (tid & 7) * 8;    // 8 output cols
    unsigned long long acc[4][4];
#pragma unroll
    for (int m = 0; m < 4; m++) {
        unsigned long long bv = pack2(bs[c0 + 2 * m], bs[c0 + 2 * m + 1]);
#pragma unroll
        for (int j = 0; j < 4; j++) acc[j][m] = bv;
    }
#pragma unroll 2
    for (int k4 = 0; k4 < 32; k4 += 4) {
        float4 a4[4];
#pragma unroll
        for (int j = 0; j < 4; j++)
            a4[j] = *(const float4*)&Xs[(ng + 32 * j) * 36 + k4];
#pragma unroll
        for (int kk = 0; kk < 4; kk++) {
            const float* w = &Ws[(k4 + kk) * 64 + c0];
            ulonglong2 wA = *(const ulonglong2*)w;
            ulonglong2 wB = *(const ulonglong2*)(w + 4);
#pragma unroll
            for (int j = 0; j < 4; j++) {
                float a = (&a4[j].x)[kk];
                unsigned long long a2 = pack2(a, a);
                acc[j][0] = ffma2(a2, wA.x, acc[j][0]);
                acc[j][1] = ffma2(a2, wA.y, acc[j][1]);
                acc[j][2] = ffma2(a2, wB.x, acc[j][2]);
                acc[j][3] = ffma2(a2, wB.y, acc[j][3]);
            }
        }
    }
#pragma unroll
    for (int j = 0; j < 4; j++) {
        int gn = n0 + ng + 32 * j;
        if (gn < NN) {
            float4 oA, oB;
            unpack2(acc[j][0], oA.x, oA.y);
            unpack2(acc[j][1], oA.z, oA.w);
            unpack2(acc[j][2], oB.x, oB.y);
            unpack2(acc[j][3], oB.z, oB.w);
            *(float4*)&g_h[gn * H + c0] = oA;
            *(float4*)&g_h[gn * H + c0 + 4] = oB;
        }
    }
}

// ---------------- softmax aggregation (warp/node, half-warp edge pairs) -
// Lanes 0-15 take even edges, 16-31 odd edges; each lane owns 4 channels
// (float4 loads). Halves merge with shfl_xor(16) at the end. Same no-max
// exp-sum math as the R5 kernel (identical per-value ops).
__global__ __launch_bounds__(256) void k_agg(const float* __restrict__ tptr,
                                             int layer, int use_h) {
    int node = blockIdx.x * 8 + (threadIdx.x >> 5);
    if (node >= NN) return;
    int lane = threadIdx.x & 31;
    int q4 = (lane & 15) * 4;  // channel base
    int h = lane >> 4;         // edge parity half
    const float* __restrict__ y = use_h ? g_h : g_y;
    float tv = tptr[layer];
    int s = g_rowptr[node], e = g_rowptr[node + 1];
    float4 hv = *(const float4*)&y[node * H + q4];
    if (s == e) {  // no incoming edges: agg = 0
        if (h == 0) *(float4*)&g_t0[node * H + q4] = hv;
        return;
    }
    float4 dA = make_float4(0.f, 0.f, 0.f, 0.f);
    float4 nA = dA, dB = dA, nB = dA;
    int i = s + h;  // this half's first edge
    for (; i + 2 < e; i += 4) {  // two edges per half per iteration
        int s0 = g_csr[i];
        int s1 = g_csr[i + 2];
        float4 v0 = *(const float4*)&y[s0 * H + q4];
        float4 v1 = *(const float4*)&y[s1 * H + q4];
        float a0 = fmaxf(v0.x, 0.f) + EPS, a1 = fmaxf(v0.y, 0.f) + EPS;
        float a2 = fmaxf(v0.z, 0.f) + EPS, a3 = fmaxf(v0.w, 0.f) + EPS;
        float b0 = fmaxf(v1.x, 0.f) + EPS, b1 = fmaxf(v1.y, 0.f) + EPS;
        float b2 = fmaxf(v1.z, 0.f) + EPS, b3 = fmaxf(v1.w, 0.f) + EPS;
        float ea0 = __expf(tv * a0), ea1 = __expf(tv * a1);
        float ea2 = __expf(tv * a2), ea3 = __expf(tv * a3);
        float eb0 = __expf(tv * b0), eb1 = __expf(tv * b1);
        float eb2 = __expf(tv * b2), eb3 = __expf(tv * b3);
        dA.x += ea0; nA.x = fmaf(a0, ea0, nA.x);
        dA.y += ea1; nA.y = fmaf(a1, ea1, nA.y);
        dA.z += ea2; nA.z = fmaf(a2, ea2, nA.z);
        dA.w += ea3; nA.w = fmaf(a3, ea3, nA.w);
        dB.x += eb0; nB.x = fmaf(b0, eb0, nB.x);
        dB.y += eb1; nB.y = fmaf(b1, eb1, nB.y);
        dB.z += eb2; nB.z = fmaf(b2, eb2, nB.z);
        dB.w += eb3; nB.w = fmaf(b3, eb3, nB.w);
    }
    if (i < e) {  // this half's last edge (if any)
        int s0 = g_csr[i];
        float4 v0 = *(const float4*)&y[s0 * H + q4];
        float a0 = fmaxf(v0.x, 0.f) + EPS, a1 = fmaxf(v0.y, 0.f) + EPS;
        float a2 = fmaxf(v0.z, 0.f) + EPS, a3 = fmaxf(v0.w, 0.f) + EPS;
        float ea0 = __expf(tv * a0), ea1 = __expf(tv * a1);
        float ea2 = __expf(tv * a2), ea3 = __expf(tv * a3);
        dA.x += ea0; nA.x = fmaf(a0, ea0, nA.x);
        dA.y += ea1; nA.y = fmaf(a1, ea1, nA.y);
        dA.z += ea2; nA.z = fmaf(a2, ea2, nA.z);
        dA.w += ea3; nA.w = fmaf(a3, ea3, nA.w);
    }
    // combine banks, then combine halves (lanes l and l+16 share channels)
    dA.x += dB.x; dA.y += dB.y; dA.z += dB.z; dA.w += dB.w;
    nA.x += nB.x; nA.y += nB.y; nA.z += nB.z; nA.w += nB.w;
    dA.x += __shfl_xor_sync(0xffffffffu, dA.x, 16);
    dA.y += __shfl_xor_sync(0xffffffffu, dA.y, 16);
    dA.z += __shfl_xor_sync(0xffffffffu, dA.z, 16);
    dA.w += __shfl_xor_sync(0xffffffffu, dA.w, 16);
    nA.x += __shfl_xor_sync(0xffffffffu, nA.x, 16);
    nA.y += __shfl_xor_sync(0xffffffffu, nA.y, 16);
    nA.z += __shfl_xor_sync(0xffffffffu, nA.z, 16);
    nA.w += __shfl_xor_sync(0xffffffffu, nA.w, 16);
    if (h == 0) {
        float4 o;
        o.x = nA.x / dA.x + hv.x;
        o.y = nA.y / dA.y + hv.y;
        o.z = nA.z / dA.z + hv.z;
        o.w = nA.w / dA.w + hv.w;
        *(float4*)&g_t0[node * H + q4] = o;
    }
}

// ---------------- fused GENConv MLP layer (R5 verbatim) ------------------
// h = (res? h:0) + relu(LN_mlp(t0@W1+b1)) @ W2 + b2 ;  y = relu(LN_next(h))
__global__ __launch_bounds__(256) void k_layer(
    const float* __restrict__ W1, const float* __restrict__ b1,
    const float* __restrict__ mlg, const float* __restrict__ mlb,
    const float* __restrict__ W2, const float* __restrict__ b2,
    const float* __restrict__ lnG, const float* __restrict__ lnB,
    int residual) {
    __shared__ float sm[11072];
    float* As = sm;           // 64 x 68 (phase 1)
    float* Wb = sm + 4352;    // 32 x 128 (phase 1, K-chunked W1)
    float* U = sm;            // 64 x 132 (phase 2, aliases As+Wb)
    float* W2b = sm + 8448;   // 32 x 64 (phase 2, K-chunked W2)
    float* sb1 = sm + 10496;  // 128
    float* smg = sm + 10624;  // 128
    float* smb = sm + 10752;  // 128
    float* sb2 = sm + 10880;  // 64
    float* slg = sm + 10944;  // 64
    float* slb = sm + 11008;  // 64

    const int tid = threadIdx.x;
    const int n0 = blockIdx.x * 64;
    const int u1 = tid & 15;
    const int ngb = (tid >> 4) * 4;  // first of this thread's 4 nodes
    const int c0 = u1 * 8;           // phase-1 column base (8 cols)
    const int c2 = u1 * 4;           // phase-2 column base (4 cols)

    // ---- load A tile (t0) + params + first W1 chunk ----
#pragma unroll
    for (int i = tid * 4; i < 4096; i += 1024) {
        int r = i >> 6, c = i & 63;
        float4 v = make_float4(0.f, 0.f, 0.f, 0.f);
        if (n0 + r < NN) v = *(const float4*)&g_t0[(n0 + r) * H + c];
        *(float4*)&As[r * 68 + c] = v;
    }
    if (tid < 128) {
        sb1[tid] = b1[tid]; smg[tid] = mlg[tid]; smb[tid] = mlb[tid];
    } else if (tid < 192) {
        int c = tid - 128;
        sb2[c] = b2[c]; slg[c] = lnG[c]; slb[c] = lnB[c];
    }
#pragma unroll
    for (int i = tid * 4; i < 4096; i += 1024)
        *(float4*)&Wb[i] = *(const float4*)&W1[i];
    __syncthreads();

    // ---- phase 1: P = t0 @ W1 + b1 (4 nodes x 8 cols per thread) ----
    unsigned long long acc[4][4];
#pragma unroll
    for (int m = 0; m < 4; m++) {
        unsigned long long bv = pack2(sb1[c0 + 2 * m], sb1[c0 + 2 * m + 1]);
#pragma unroll
        for (int j = 0; j < 4; j++) acc[j][m] = bv;
    }
#pragma unroll 1
    for (int kc = 0; kc < 2; kc++) {
        if (kc == 1) {
            __syncthreads();
#pragma unroll
            for (int i = tid * 4; i < 4096; i += 1024)
                *(float4*)&Wb[i] = *(const float4*)&W1[4096 + i];
            __syncthreads();
        }
        const int kb = kc * 32;
#pragma unroll 2
        for (int k4 = 0; k4 < 32; k4 += 4) {
            float4 a4[4];
#pragma unroll
            for (int j = 0; j < 4; j++)
                a4[j] = *(const float4*)&As[(ngb + j) * 68 + kb + k4];
#pragma unroll
            for (int kk = 0; kk < 4; kk++) {
                const float* w = &Wb[(k4 + kk) * 128 + c0];
                ulonglong2 wA = *(const ulonglong2*)w;
                ulonglong2 wB = *(const ulonglong2*)(w + 4);
#pragma unroll
                for (int j = 0; j < 4; j++) {
                    float a = (&a4[j].x)[kk];
                    unsigned long long a2 = pack2(a, a);
                    acc[j][0] = ffma2(a2, wA.x, acc[j][0]);
                    acc[j][1] = ffma2(a2, wA.y, acc[j][1]);
                    acc[j][2] = ffma2(a2, wB.x, acc[j][2]);
                    acc[j][3] = ffma2(a2, wB.y, acc[j][3]);
                }
            }
        }
    }

    // ---- LN(128) + ReLU in registers ----
    float v1[4][8];
#pragma unroll
    for (int j = 0; j < 4; j++)
#pragma unroll
        for (int m = 0; m < 4; m++)
            unpack2(acc[j][m], v1[j][2 * m], v1[j][2 * m + 1]);
    float mean1[4], rs1[4];
#pragma unroll
    for (int j = 0; j < 4; j++) {
        float s = 0.f;
#pragma unroll
        for (int m = 0; m < 8; m++) s += v1[j][m];
        mean1[j] = red16(s) * (1.0f / 128.0f);
    }
#pragma unroll
    for (int j = 0; j < 4; j++) {
        float q = 0.f;
#pragma unroll
        for (int m = 0; m < 8; m++) {
            float d = v1[j][m] - mean1[j];
            q += d * d;
        }
        rs1[j] = rsqrtf(red16(q) * (1.0f / 128.0f) + LN_EPS);
    }
    __syncthreads();  // all As/Wb reads done; safe to alias as U
#pragma unroll
    for (int j = 0; j < 4; j++) {
        float o[8];
#pragma unroll
        for (int m = 0; m < 8; m++) {
            int c = c0 + m;
            o[m] = fmaxf(fmaf((v1[j][m] - mean1[j]) * rs1[j], smg[c], smb[c]), 0.f);
        }
        *(float4*)&U[(ngb + j) * 132 + c0] = make_float4(o[0], o[1], o[2], o[3]);
        *(float4*)&U[(ngb + j) * 132 + c0 + 4] = make_float4(o[4], o[5], o[6], o[7]);
    }
    __syncthreads();

    // ---- phase 2: out = U @ W2 + b2 (4 nodes x 4 cols per thread) ----
    unsigned long long acc2[4][2];
#pragma unroll
    for (int m = 0; m < 2; m++) {
        unsigned long long bv = pack2(sb2[c2 + 2 * m], sb2[c2 + 2 * m + 1]);
#pragma unroll
        for (int j = 0; j < 4; j++) acc2[j][m] = bv;
    }
#pragma unroll 1
    for (int kc = 0; kc < 4; kc++) {
#pragma unroll
        for (int i = tid * 4; i < 2048; i += 1024)
            *(float4*)&W2b[i] = *(const float4*)&W2[kc * 2048 + i];
        __syncthreads();
#pragma unroll 2
        for (int k4 = 0; k4 < 32; k4 += 4) {
            float4 a4[4];
#pragma unroll
            for (int j = 0; j < 4; j++)
                a4[j] = *(const float4*)&U[(ngb + j) * 132 + kc * 32 + k4];
#pragma unroll
            for (int kk = 0; kk < 4; kk++) {
                ulonglong2 w = *(const ulonglong2*)&W2b[(k4 + kk) * 64 + c2];
#pragma unroll
                for (int j = 0; j < 4; j++) {
                    float a = (&a4[j].x)[kk];
                    unsigned long long a2 = pack2(a, a);
                    acc2[j][0] = ffma2(a2, w.x, acc2[j][0]);
                    acc2[j][1] = ffma2(a2, w.y, acc2[j][1]);
                }
            }
        }
        __syncthreads();
    }

    // ---- epilogue: residual, write h, then LN(64)+ReLU -> y ----
    float hv[4][4];
#pragma unroll
    for (int j = 0; j < 4; j++) {
        unpack2(acc2[j][0], hv[j][0], hv[j][1]);
        unpack2(acc2[j][1], hv[j][2], hv[j][3]);
        int gn = n0 + ngb + j;
        if (gn < NN) {
            if (residual) {
                float4 o = *(const float4*)&g_h[gn * H + c2];
                hv[j][0] += o.x; hv[j][1] += o.y; hv[j][2] += o.z; hv[j][3] += o.w;
            }
            *(float4*)&g_h[gn * H + c2] =
                make_float4(hv[j][0], hv[j][1], hv[j][2], hv[j][3]);
        }
    }
#pragma unroll
    for (int j = 0; j < 4; j++) {
        float s = hv[j][0] + hv[j][1] + hv[j][2] + hv[j][3];
        float mean = red16(s) * (1.0f / 64.0f);
        float q = 0.f;
#pragma unroll
        for (int m = 0; m < 4; m++) {
            float d = hv[j][m] - mean;
            q += d * d;
        }
        float rs = rsqrtf(red16(q) * (1.0f / 64.0f) + LN_EPS);
        int gn = n0 + ngb + j;
        if (gn < NN) {
            float4 o;
            o.x = fmaxf(fmaf((hv[j][0] - mean) * rs, slg[c2], slb[c2]), 0.f);
            o.y = fmaxf(fmaf((hv[j][1] - mean) * rs, slg[c2 + 1], slb[c2 + 1]), 0.f);
            o.z = fmaxf(fmaf((hv[j][2] - mean) * rs, slg[c2 + 2], slb[c2 + 2]), 0.f);
            o.w = fmaxf(fmaf((hv[j][3] - mean) * rs, slg[c2 + 3], slb[c2 + 3]), 0.f);
            *(float4*)&g_y[gn * H + c2] = o;
        }
    }
}

// ---------------- heads: 33 outputs per node, global max over 16 --------
__global__ __launch_bounds__(256) void k_heads(const float* __restrict__ gW,
                                               const float* __restrict__ gb,
                                               const float* __restrict__ nW,
                                               const float* __restrict__ nb,
                                               float* __restrict__ dout) {
    __shared__ float As[32][65];
    __shared__ float Ws[64][33];
    __shared__ float bsh[33];
    __shared__ unsigned smax[16];
    const int tid = threadIdx.x;
    const int n0 = blockIdx.x * 32;
#pragma unroll
    for (int i = tid * 4; i < 2048; i += 1024) {
        int r = i >> 6, c = i & 63;
        float4 v = make_float4(0.f, 0.f, 0.f, 0.f);
        if (n0 + r < NN) v = *(const float4*)&g_y[(n0 + r) * H + c];
        As[r][c] = v.x;
        As[r][c + 1] = v.y;
        As[r][c + 2] = v.z;
        As[r][c + 3] = v.w;
    }
    for (int i = tid; i < 64 * 33; i += 256) {
        int k = i / 33, c = i % 33;
        Ws[k][c] = (c < 16) ? gW[k * 16 + c] : nW[k * 17 + (c - 16)];
    }
    if (tid < 33) bsh[tid] = (tid < 16) ? gb[tid] : nb[tid - 16];
    if (tid < 16) smax[tid] = 0u;
    __syncthreads();

    for (int o = tid; o < 32 * 33; o += 256) {
        int node = o / 33, c = o % 33;
        float acc = bsh[c];
#pragma unroll 16
        for (int k = 0; k < 64; k++) acc = fmaf(As[node][k], Ws[k][c], acc);
        int gn = n0 + node;
        if (gn < NN) {
            if (c >= 16) {
                dout[16 + gn * 17 + (c - 16)] = acc;
            } else {
                atomicMax(&smax[c], fenc(acc));
            }
        }
    }
    __syncthreads();
    if (tid < 16) atomicMax(&g_gmax[tid], smax[tid]);
}

__global__ void k_decode(float* __restrict__ dout) {
    if (threadIdx.x < 16) dout[threadIdx.x] = fdec(g_gmax[threadIdx.x]);
}

// ---------------- host launcher ----------------
extern "C" void kernel_launch(void* const* d_in, const int* in_sizes, int n_in,
                              void* d_out, int out_size) {
    const float* x = (const float*)d_in[0];
    const float* node_W = (const float*)d_in[1];
    const float* node_b = (const float*)d_in[2];
    const float* W1 = (const float*)d_in[3];
    const float* b1 = (const float*)d_in[4];
    const float* mlg = (const float*)d_in[5];
    const float* mlb = (const float*)d_in[6];
    const float* W2 = (const float*)d_in[7];
    const float* b2 = (const float*)d_in[8];
    const float* t = (const float*)d_in[9];
    const float* lng = (const float*)d_in[10];
    const float* lnb = (const float*)d_in[11];
    const int* ei = (const int*)d_in[12];
    const float* gW = (const float*)d_in[13];
    const float* gb = (const float*)d_in[14];
    const float* nW = (const float*)d_in[15];
    const float* nb = (const float*)d_in[16];
    float* out = (float*)d_out;

    const int GEMM_BLKS = (NN + 31) / 32;    // 1563
    const int ENC_BLKS = (NN + 127) / 128;   // 391
    const int TILE_BLKS = (NN + 63) / 64;    // 782
    const int WARP_BLKS = (NN + 7) / 8;      // 6250
    const int E_BLKS = (EE + 255) / 256;     // 3125

    k_init<<<(NN + 255) / 256, 256>>>();
    k_deg<<<E_BLKS, 256>>>(ei);
    k_scan<<<1, 1024>>>();
    k_fill<<<E_BLKS, 256>>>(ei);

    k_encoder<<<ENC_BLKS, 256>>>(x, node_W, node_b);

    for (int L = 0; L < 4; L++) {
        k_agg<<<WARP_BLKS, 256>>>(t, L, L == 0 ? 1 : 0);
        int nxt = (L + 1) & 3;  // next layer's DeepGCN LN; L=3 -> final LN (idx 0)
        k_layer<<<TILE_BLKS, 256>>>(W1 + L * H * H2, b1 + L * H2,
                                    mlg + L * H2, mlb + L * H2,
                                    W2 + L * H2 * H, b2 + L * H,
                                    lng + nxt * H, lnb + nxt * H, L > 0 ? 1 : 0);
    }

    k_heads<<<GEMM_BLKS, 256>>>(gW, gb, nW, nb, out);
    k_decode<<<1, 32>>>(out);
}